// round 3
// baseline (speedup 1.0000x reference)
#include <cuda_runtime.h>
#include <cstdint>

// Per-batch class-presence bitmasks (bits 0..5), B=64. Written by each block,
// read by the finishing block via L2 (__ldcg) — L1 is not cross-SM coherent.
__device__ unsigned g_masks[64];
// Completion counter for the last-block-done pattern. Invariant: 0 at entry,
// restored to 0 by the finishing block => deterministic across graph replays.
__device__ unsigned g_done = 0;

// ---------------------------------------------------------------------------
// Fused kernel: one block per batch.
// Phase 1 (all blocks): OR-reduce int32 labels (0..5) into a 6-bit presence
//   mask. Early exit: presence OR is monotone — once the accumulated mask is
//   0x3F the rest of the batch cannot change it. Uniform labels hit 0x3F in
//   the first 1024-label chunk (p_miss ~ 6*(5/6)^1024 ≈ 1e-81); worst case
//   degrades to a full scan (still correct, data-independent semantics).
// Phase 2 (last finishing block only): 384-term BCE with torch's log clamp
//   at -100, mean-reduced, written to out[0]. Counter reset to 0.
// ---------------------------------------------------------------------------
__global__ void se_loss_fused_kernel(const int* __restrict__ target,
                                     const float* __restrict__ se_pred,
                                     float* __restrict__ out,
                                     int n_vec4_per_batch, int n_batches,
                                     int n_terms) {
    const int b   = blockIdx.x;
    const int tid = threadIdx.x;
    const int4* __restrict__ t4 =
        reinterpret_cast<const int4*>(target) + (long long)b * n_vec4_per_batch;

    __shared__ unsigned smask;
    __shared__ unsigned s_is_last;
    if (tid == 0) smask = 0u;
    __syncthreads();

    // ---- Phase 1: presence mask ----
    unsigned local = 0u;
    const int PER_ITER = 256;  // int4 per chunk = 1024 labels
    for (int base4 = 0; base4 < n_vec4_per_batch; base4 += PER_ITER) {
        int idx = base4 + tid;
        if (idx < n_vec4_per_batch) {
            int4 v = t4[idx];
            local |= (1u << (v.x & 31)) | (1u << (v.y & 31)) |
                     (1u << (v.z & 31)) | (1u << (v.w & 31));
        }
        unsigned wm = __reduce_or_sync(0xffffffffu, local);
        if ((tid & 31) == 0) atomicOr(&smask, wm);
        __syncthreads();
        if ((smask & 0x3Fu) == 0x3Fu) break;   // all 6 classes seen
        __syncthreads();
    }

    // ---- Publish mask, detect last block ----
    if (tid == 0) {
        atomicExch(&g_masks[b], smask);    // L2-visible store
        __threadfence();                   // release: mask before counter
        unsigned prev = atomicAdd(&g_done, 1u);
        s_is_last = (prev == (unsigned)(n_batches - 1)) ? 1u : 0u;
    }
    __syncthreads();
    if (!s_is_last) return;

    // ---- Phase 2: BCE loss (finishing block only) ----
    __threadfence();  // acquire side
    float acc = 0.0f;
    for (int i = tid; i < n_terms; i += blockDim.x) {
        const int bb = i / 6;
        const int cc = i - bb * 6;
        const unsigned m = __ldcg(&g_masks[bb]);   // bypass L1 (cross-SM)
        const float p  = se_pred[i];
        const float t  = (float)((m >> cc) & 1u);
        const float lp  = fmaxf(logf(p),    -100.0f);
        const float l1p = fmaxf(log1pf(-p), -100.0f);
        acc += -(t * lp + (1.0f - t) * l1p);
    }

    // Block reduction: 8 warps -> shared -> warp 0.
    __shared__ float sh[8];
    #pragma unroll
    for (int o = 16; o > 0; o >>= 1) acc += __shfl_down_sync(0xffffffffu, acc, o);
    if ((tid & 31) == 0) sh[tid >> 5] = acc;
    __syncthreads();
    if (tid < 32) {
        float s = (tid < 8) ? sh[tid] : 0.0f;
        #pragma unroll
        for (int o = 4; o > 0; o >>= 1) s += __shfl_down_sync(0xffffffffu, s, o);
        if (tid == 0) {
            out[0] = s / (float)n_terms;
            g_done = 0u;                   // restore invariant for next replay
        }
    }
}

// ---------------------------------------------------------------------------
extern "C" void kernel_launch(void* const* d_in, const int* in_sizes, int n_in,
                              void* d_out, int out_size) {
    // Resolve inputs by size: se_pred has 64*6 = 384 elements; target is huge.
    int se_idx = 0, tg_idx = 1;
    if (n_in >= 2 && in_sizes[0] > in_sizes[1]) { se_idx = 1; tg_idx = 0; }

    const float* se_pred = (const float*)d_in[se_idx];
    const int*   target  = (const int*)d_in[tg_idx];
    float* out = (float*)d_out;

    const int n_terms   = in_sizes[se_idx];        // 384
    const int B         = n_terms / 6;             // 64
    const int per_batch = in_sizes[tg_idx] / B;    // 262144 int32 labels
    const int n_vec4    = per_batch / 4;           // int4 count per batch

    se_loss_fused_kernel<<<B, 256>>>(target, se_pred, out, n_vec4, B, n_terms);
}

// round 4
// speedup vs baseline: 1.3037x; 1.3037x over previous
#include <cuda_runtime.h>
#include <cstdint>

// ---------------------------------------------------------------------------
// Single-block fused kernel (1024 threads, one SM, no global sync needed).
//
// Phase 1: 32 warps, each owns ceil(B/32) batches (2 for B=64), 16 lanes per
//   batch. Per iteration each lane loads int4 (4 labels) -> 64 labels per
//   batch. Both batches' 6-bit presence masks are packed into one u32
//   (bits 0-5 and 16-21) and OR-reduced warp-wide in one __reduce_or_sync.
//   Early exit when both masks complete: presence OR is monotone, so skipped
//   data cannot change the result. Uniform labels finish in 1-2 iterations
//   (p_miss(128 labels) ~ 4e-10); adversarial data degrades to a full scan
//   (still correct). Warps iterate independently — no barrier in the loop.
//
// Phase 2: masks land in shared; after one __syncthreads the first 384
//   threads compute the BCE terms (torch log clamp at -100) and block-reduce
//   the mean into out[0]. se_pred is prefetched before phase 1 so its DRAM
//   latency overlaps the target scan.
// ---------------------------------------------------------------------------
__global__ void __launch_bounds__(1024, 1)
se_loss_oneblock_kernel(const int* __restrict__ target,
                        const float* __restrict__ se_pred,
                        float* __restrict__ out,
                        int n_vec4_per_batch, int n_batches, int n_terms) {
    const int tid     = threadIdx.x;
    const int wid     = tid >> 5;
    const int lane    = tid & 31;
    const int half    = lane >> 4;      // 0 or 1: which batch of the pair
    const int sublane = lane & 15;

    __shared__ unsigned smasks[64];
    __shared__ float    sred[12];

    // Prefetch se_pred while the target scan is in flight.
    float p = (tid < n_terms) ? se_pred[tid] : 0.5f;

    // ---- Phase 1: presence masks, 2 batches per warp ----
    const int pairs = (n_batches + 63) >> 6;          // outer batches per warp slot
    for (int j = 0; j < pairs; j++) {
        const int bpair = wid + (j << 5);             // pair index 0..31
        const int b     = (bpair << 1) + half;        // this half-warp's batch
        const bool valid = (b < n_batches);

        const int4* __restrict__ t4 = valid
            ? reinterpret_cast<const int4*>(target) + (long long)b * n_vec4_per_batch
            : nullptr;

        const unsigned DONE = 0x003F003Fu;
        unsigned acc = valid ? 0u : (0x3Fu << (half << 4)); // invalid half reads done
        const int shamt = half << 4;
        const int max_iter = (n_vec4_per_batch + 15) >> 4;

        for (int it = 0; it < max_iter; it++) {
            int idx = (it << 4) + sublane;
            if (valid && idx < n_vec4_per_batch) {
                int4 v = t4[idx];
                unsigned bits = (1u << (v.x & 31)) | (1u << (v.y & 31)) |
                                (1u << (v.z & 31)) | (1u << (v.w & 31));
                acc |= (bits & 0x3Fu) << shamt;
            }
            acc = __reduce_or_sync(0xffffffffu, acc);
            if ((acc & DONE) == DONE) break;
        }

        if (lane == 0 && (bpair << 1) < n_batches) {
            smasks[bpair << 1] = acc & 0x3Fu;
            if ((bpair << 1) + 1 < n_batches)
                smasks[(bpair << 1) + 1] = (acc >> 16) & 0x3Fu;
        }
    }
    __syncthreads();

    // ---- Phase 2: BCE over 384 (batch, class) terms ----
    float v = 0.0f;
    if (tid < n_terms) {
        const int bb = tid / 6;
        const int cc = tid - bb * 6;
        const float t   = (float)((smasks[bb] >> cc) & 1u);
        const float lp  = fmaxf(logf(p),    -100.0f);
        const float l1p = fmaxf(log1pf(-p), -100.0f);
        v = -(t * lp + (1.0f - t) * l1p);
    }
    if (wid < 12) {                       // only warps holding terms reduce
        #pragma unroll
        for (int o = 16; o > 0; o >>= 1) v += __shfl_down_sync(0xffffffffu, v, o);
        if (lane == 0) sred[wid] = v;
    }
    __syncthreads();
    if (tid < 32) {
        float s = (tid < 12) ? sred[tid] : 0.0f;
        #pragma unroll
        for (int o = 8; o > 0; o >>= 1) s += __shfl_down_sync(0xffffffffu, s, o);
        if (tid == 0) out[0] = s / (float)n_terms;
    }
}

// ---------------------------------------------------------------------------
extern "C" void kernel_launch(void* const* d_in, const int* in_sizes, int n_in,
                              void* d_out, int out_size) {
    // Resolve inputs by size: se_pred has 64*6 = 384 elements; target is huge.
    int se_idx = 0, tg_idx = 1;
    if (n_in >= 2 && in_sizes[0] > in_sizes[1]) { se_idx = 1; tg_idx = 0; }

    const float* se_pred = (const float*)d_in[se_idx];
    const int*   target  = (const int*)d_in[tg_idx];
    float* out = (float*)d_out;

    const int n_terms   = in_sizes[se_idx];        // 384
    const int B         = n_terms / 6;             // 64
    const int per_batch = in_sizes[tg_idx] / B;    // 262144 int32 labels
    const int n_vec4    = per_batch / 4;           // int4 count per batch

    se_loss_oneblock_kernel<<<1, 1024>>>(target, se_pred, out, n_vec4, B, n_terms);
}